// round 4
// baseline (speedup 1.0000x reference)
#include <cuda_runtime.h>

// Dempster-Shafer evidential layer — packed f32x2, 4 points/thread (2 pairs).
// x: [B=2, C=16, 64,64,64] f32;  W: [20,16];  BETA: [20,4];  alpha,gamma: [20,1]
// out: [B, 5, 64,64,64] f32
//
// Exponent folding: s_k = 2^( hgn_k*||x||^2 + <x, sc_k*W_k> + c2_k )
//   sc_k  = gamma_k^2 * log2(e)            (so dot term = -gn*xw)
//   hgn_k = -0.5*sc_k
//   c2_k  = -0.5*sc_k*||W_k||^2 + log2(alphap_k)
// Q_m = prod_k (U[k][m]*s_k + (1-s_k)),  O = prod_k (1-s_k)
// out = normalize([Q_m - O, O])

#define CC   16
#define KK   20
#define MM   4
#define HWD  (64*64*64)        // 262144
#define QWD  (HWD/4)           // 65536 groups-of-4 per volume
#define NGRP (2*QWD)           // 131072 threads total

typedef unsigned long long u64;

__device__ __forceinline__ u64 fma2(u64 a, u64 b, u64 c) {
    u64 d; asm("fma.rn.f32x2 %0, %1, %2, %3;" : "=l"(d) : "l"(a), "l"(b), "l"(c)); return d;
}
__device__ __forceinline__ u64 mul2(u64 a, u64 b) {
    u64 d; asm("mul.rn.f32x2 %0, %1, %2;" : "=l"(d) : "l"(a), "l"(b)); return d;
}
__device__ __forceinline__ u64 add2(u64 a, u64 b) {
    u64 d; asm("add.rn.f32x2 %0, %1, %2;" : "=l"(d) : "l"(a), "l"(b)); return d;
}
__device__ __forceinline__ u64 pk(float lo, float hi) {
    u64 r; asm("mov.b64 %0, {%1,%2};" : "=l"(r) : "f"(lo), "f"(hi)); return r;
}
__device__ __forceinline__ void upk(u64 v, float& lo, float& hi) {
    asm("mov.b64 {%0,%1}, %2;" : "=f"(lo), "=f"(hi) : "l"(v));
}
__device__ __forceinline__ float ex2f(float x) {
    float r; asm("ex2.approx.f32 %0, %1;" : "=f"(r) : "f"(x)); return r;
}
__device__ __forceinline__ float lg2f(float x) {
    float r; asm("lg2.approx.f32 %0, %1;" : "=f"(r) : "f"(x)); return r;
}
__device__ __forceinline__ float rcpf(float x) {
    float r; asm("rcp.approx.f32 %0, %1;" : "=f"(r) : "f"(x)); return r;
}

#define ONEp  0x3F8000003F800000ull
#define NEG1p 0xBF800000BF800000ull
#define L2E   1.4426950408889634f

__global__ __launch_bounds__(256) void ds_kernel(
    const float* __restrict__ x,
    const float* __restrict__ Wp,
    const float* __restrict__ BETA,
    const float* __restrict__ alpha,
    const float* __restrict__ gamma,
    float* __restrict__ out)
{
    __shared__ ulonglong2 sW2[CC][KK / 2];   // (sc_k*W, sc_k*W) dup pairs, 2 k per vec
    __shared__ ulonglong2 sKC[KK][3];        // [(hgn,c2)] [(u0,u1)] [(u2,u3)] dup-packed

    const int tid = threadIdx.x;

    {
        u64* wbase = (u64*)&sW2[0][0];       // row length = KK u64
        for (int i = tid; i < CC * KK; i += 256) {
            int k = i % KK, c = i / KK;
            float g  = gamma[k];
            float sc = g * g * L2E;
            float w  = Wp[k * CC + c] * sc;
            wbase[c * KK + k] = pk(w, w);
        }
    }
    if (tid < KK) {
        const int k = tid;
        float w2 = 0.f;
        #pragma unroll
        for (int c = 0; c < CC; c++) { float v = Wp[k * CC + c]; w2 = fmaf(v, v, w2); }
        float g   = gamma[k];
        float sc  = g * g * L2E;
        float hgn = -0.5f * sc;
        float a   = alpha[k];
        float ap  = 0.99f * rcpf(1.0f + ex2f(-a * L2E));
        float c2  = hgn * w2 + lg2f(ap);
        float b2[MM]; float bs = 0.f;
        #pragma unroll
        for (int m = 0; m < MM; m++) { float b = BETA[k * MM + m]; b2[m] = b * b; bs += b2[m]; }
        float inv = __fdividef(1.0f, bs);
        sKC[k][0] = make_ulonglong2(pk(hgn, hgn), pk(c2, c2));
        sKC[k][1] = make_ulonglong2(pk(b2[0]*inv, b2[0]*inv), pk(b2[1]*inv, b2[1]*inv));
        sKC[k][2] = make_ulonglong2(pk(b2[2]*inv, b2[2]*inv), pk(b2[3]*inv, b2[3]*inv));
    }
    __syncthreads();

    const int gidx = blockIdx.x * 256 + tid;   // group-of-4-points index
    const int b    = gidx >> 16;               // / QWD
    const int sq   = gidx & (QWD - 1);
    const ulonglong2* xb = (const ulonglong2*)x + ((size_t)b * CC << 16) + sq;

    // A{0,1}[k] = <x, sc_k*W_k> for pair0/pair1; x2{a,b} = ||x||^2 packed
    u64 A0[KK], A1[KK];
    #pragma unroll
    for (int k = 0; k < KK; k++) { A0[k] = 0ull; A1[k] = 0ull; }
    u64 x2a = 0ull, x2b = 0ull;

    #pragma unroll
    for (int c = 0; c < CC; c++) {
        ulonglong2 xv = __ldg(xb + ((size_t)c << 16));   // LDG.128: 4 consecutive points
        x2a = fma2(xv.x, xv.x, x2a);
        x2b = fma2(xv.y, xv.y, x2b);
        #pragma unroll
        for (int k2 = 0; k2 < KK / 2; k2++) {
            ulonglong2 w = sW2[c][k2];                   // LDS.128 feeds 4 fma2
            A0[2*k2]   = fma2(xv.x, w.x, A0[2*k2]);
            A1[2*k2]   = fma2(xv.y, w.x, A1[2*k2]);
            A0[2*k2+1] = fma2(xv.x, w.y, A0[2*k2+1]);
            A1[2*k2+1] = fma2(xv.y, w.y, A1[2*k2+1]);
        }
    }

    u64 O0 = ONEp, P00 = ONEp, P01 = ONEp, P02 = ONEp, P03 = ONEp;
    u64 O1 = ONEp, P10 = ONEp, P11 = ONEp, P12 = ONEp, P13 = ONEp;

    #pragma unroll
    for (int k = 0; k < KK; k++) {
        ulonglong2 qa = sKC[k][0];
        u64 t0 = add2(fma2(qa.x, x2a, qa.y), A0[k]);     // log2-domain exponent
        u64 t1 = add2(fma2(qa.x, x2b, qa.y), A1[k]);
        float e00, e01, e10, e11;
        upk(t0, e00, e01); upk(t1, e10, e11);
        u64 s0 = pk(ex2f(e00), ex2f(e01));
        u64 s1 = pk(ex2f(e10), ex2f(e11));
        u64 o0 = fma2(s0, NEG1p, ONEp);                  // 1 - s
        u64 o1 = fma2(s1, NEG1p, ONEp);
        ulonglong2 qb = sKC[k][1];
        ulonglong2 qc = sKC[k][2];
        O0 = mul2(O0, o0);                               O1 = mul2(O1, o1);
        P00 = mul2(P00, fma2(qb.x, s0, o0));             P10 = mul2(P10, fma2(qb.x, s1, o1));
        P01 = mul2(P01, fma2(qb.y, s0, o0));             P11 = mul2(P11, fma2(qb.y, s1, o1));
        P02 = mul2(P02, fma2(qc.x, s0, o0));             P12 = mul2(P12, fma2(qc.x, s1, o1));
        P03 = mul2(P03, fma2(qc.y, s0, o0));             P13 = mul2(P13, fma2(qc.y, s1, o1));
    }

    const u64 nO0 = mul2(O0, NEG1p), nO1 = mul2(O1, NEG1p);
    u64 f00 = add2(P00, nO0), f01 = add2(P01, nO0), f02 = add2(P02, nO0), f03 = add2(P03, nO0);
    u64 f10 = add2(P10, nO1), f11 = add2(P11, nO1), f12 = add2(P12, nO1), f13 = add2(P13, nO1);
    u64 sum0 = add2(add2(add2(f00, f01), add2(f02, f03)), O0);
    u64 sum1 = add2(add2(add2(f10, f11), add2(f12, f13)), O1);
    float sa, sb, sc2, sd;
    upk(sum0, sa, sb); upk(sum1, sc2, sd);
    const u64 inv0 = pk(rcpf(sa), rcpf(sb));
    const u64 inv1 = pk(rcpf(sc2), rcpf(sd));

    ulonglong2* ob = (ulonglong2*)out + ((size_t)b * (MM + 1) << 16) + sq;
    ob[(size_t)0 << 16] = make_ulonglong2(mul2(f00, inv0), mul2(f10, inv1));
    ob[(size_t)1 << 16] = make_ulonglong2(mul2(f01, inv0), mul2(f11, inv1));
    ob[(size_t)2 << 16] = make_ulonglong2(mul2(f02, inv0), mul2(f12, inv1));
    ob[(size_t)3 << 16] = make_ulonglong2(mul2(f03, inv0), mul2(f13, inv1));
    ob[(size_t)4 << 16] = make_ulonglong2(mul2(O0,  inv0), mul2(O1,  inv1));
}

extern "C" void kernel_launch(void* const* d_in, const int* in_sizes, int n_in,
                              void* d_out, int out_size)
{
    const float* x     = (const float*)d_in[0];
    const float* Wp    = (const float*)d_in[1];
    const float* BETA  = (const float*)d_in[2];
    const float* alpha = (const float*)d_in[3];
    const float* gamma = (const float*)d_in[4];
    float* out = (float*)d_out;

    ds_kernel<<<NGRP / 256, 256>>>(x, Wp, BETA, alpha, gamma, out);
}

// round 6
// speedup vs baseline: 1.0982x; 1.0982x over previous
#include <cuda_runtime.h>

// Dempster-Shafer evidential layer — packed f32x2, 4 points/thread, K split
// into 2 passes of 10 to halve live accumulator registers.
// x: [B=2, C=16, 64,64,64] f32;  W: [20,16];  BETA: [20,4];  alpha,gamma: [20,1]
// out: [B, 5, 64,64,64] f32
//
// s_k = 2^( hgn_k*||x||^2 + <x, sc_k*W_k> + c2_k ),  sc_k = gamma_k^2*log2e,
// hgn_k = -0.5*sc_k,  c2_k = hgn_k*||W_k||^2 + log2(alphap_k)
// Q_m = prod_k (U[k][m]*s_k + (1-s_k)),  O = prod_k (1-s_k)
// out = normalize([Q_m - O, O])

#define CC   16
#define KK   20
#define KH   10                // prototypes per pass
#define MM   4
#define HWD  (64*64*64)        // 262144
#define QWD  (HWD/4)           // 65536 groups-of-4 per volume
#define NTHR (2*QWD)           // 131072 threads total
#define BLK  128

typedef unsigned long long u64;

__device__ __forceinline__ u64 fma2(u64 a, u64 b, u64 c) {
    u64 d; asm("fma.rn.f32x2 %0, %1, %2, %3;" : "=l"(d) : "l"(a), "l"(b), "l"(c)); return d;
}
__device__ __forceinline__ u64 mul2(u64 a, u64 b) {
    u64 d; asm("mul.rn.f32x2 %0, %1, %2;" : "=l"(d) : "l"(a), "l"(b)); return d;
}
__device__ __forceinline__ u64 add2(u64 a, u64 b) {
    u64 d; asm("add.rn.f32x2 %0, %1, %2;" : "=l"(d) : "l"(a), "l"(b)); return d;
}
__device__ __forceinline__ u64 pk(float lo, float hi) {
    u64 r; asm("mov.b64 %0, {%1,%2};" : "=l"(r) : "f"(lo), "f"(hi)); return r;
}
__device__ __forceinline__ void upk(u64 v, float& lo, float& hi) {
    asm("mov.b64 {%0,%1}, %2;" : "=f"(lo), "=f"(hi) : "l"(v));
}
__device__ __forceinline__ float ex2f(float x) {
    float r; asm("ex2.approx.f32 %0, %1;" : "=f"(r) : "f"(x)); return r;
}
__device__ __forceinline__ float lg2f(float x) {
    float r; asm("lg2.approx.f32 %0, %1;" : "=f"(r) : "f"(x)); return r;
}
__device__ __forceinline__ float rcpf(float x) {
    float r; asm("rcp.approx.f32 %0, %1;" : "=f"(r) : "f"(x)); return r;
}

#define ONEp  0x3F8000003F800000ull
#define NEG1p 0xBF800000BF800000ull
#define L2E   1.4426950408889634f

__global__ __launch_bounds__(BLK, 4) void ds_kernel(
    const float* __restrict__ x,
    const float* __restrict__ Wp,
    const float* __restrict__ BETA,
    const float* __restrict__ alpha,
    const float* __restrict__ gamma,
    float* __restrict__ out)
{
    __shared__ ulonglong2 sW2[CC][KK / 2];   // dup-packed scaled weights, 2 k per vec
    __shared__ ulonglong2 sKC[KK][3];        // [(hgn,c2)] [(u0,u1)] [(u2,u3)] dup-packed

    const int tid = threadIdx.x;

    {
        u64* wbase = (u64*)&sW2[0][0];       // row length = KK u64
        for (int i = tid; i < CC * KK; i += BLK) {
            int k = i % KK, c = i / KK;
            float g  = gamma[k];
            float sc = g * g * L2E;
            float w  = Wp[k * CC + c] * sc;
            wbase[c * KK + k] = pk(w, w);
        }
    }
    if (tid < KK) {
        const int k = tid;
        float w2 = 0.f;
        #pragma unroll
        for (int c = 0; c < CC; c++) { float v = Wp[k * CC + c]; w2 = fmaf(v, v, w2); }
        float g   = gamma[k];
        float sc  = g * g * L2E;
        float hgn = -0.5f * sc;
        float a   = alpha[k];
        float ap  = 0.99f * rcpf(1.0f + ex2f(-a * L2E));
        float c2  = hgn * w2 + lg2f(ap);
        float b2[MM]; float bs = 0.f;
        #pragma unroll
        for (int m = 0; m < MM; m++) { float b = BETA[k * MM + m]; b2[m] = b * b; bs += b2[m]; }
        float inv = __fdividef(1.0f, bs);
        sKC[k][0] = make_ulonglong2(pk(hgn, hgn), pk(c2, c2));
        sKC[k][1] = make_ulonglong2(pk(b2[0]*inv, b2[0]*inv), pk(b2[1]*inv, b2[1]*inv));
        sKC[k][2] = make_ulonglong2(pk(b2[2]*inv, b2[2]*inv), pk(b2[3]*inv, b2[3]*inv));
    }
    __syncthreads();

    const int gidx = blockIdx.x * BLK + tid;   // group-of-4-points index
    const int b    = gidx >> 16;               // / QWD
    const int sq   = gidx & (QWD - 1);
    const ulonglong2* xb = (const ulonglong2*)x + ((size_t)b * CC << 16) + sq;

    u64 O0 = ONEp, P00 = ONEp, P01 = ONEp, P02 = ONEp, P03 = ONEp;
    u64 O1 = ONEp, P10 = ONEp, P11 = ONEp, P12 = ONEp, P13 = ONEp;
    u64 x2a = 0ull, x2b = 0ull;

    #pragma unroll
    for (int half = 0; half < 2; half++) {
        // dot-product pass over KH prototypes (10 accumulators per pair)
        u64 A0[KH], A1[KH];
        #pragma unroll
        for (int j = 0; j < KH; j++) { A0[j] = 0ull; A1[j] = 0ull; }

        #pragma unroll
        for (int c = 0; c < CC; c++) {
            ulonglong2 xv = __ldg(xb + ((size_t)c << 16));  // LDG.128 (pass 2: L1 hit)
            if (half == 0) {
                x2a = fma2(xv.x, xv.x, x2a);
                x2b = fma2(xv.y, xv.y, x2b);
            }
            #pragma unroll
            for (int j2 = 0; j2 < KH / 2; j2++) {
                ulonglong2 w = sW2[c][half * (KH / 2) + j2];  // LDS.128 feeds 4 fma2
                A0[2*j2]   = fma2(xv.x, w.x, A0[2*j2]);
                A1[2*j2]   = fma2(xv.y, w.x, A1[2*j2]);
                A0[2*j2+1] = fma2(xv.x, w.y, A0[2*j2+1]);
                A1[2*j2+1] = fma2(xv.y, w.y, A1[2*j2+1]);
            }
        }

        #pragma unroll
        for (int j = 0; j < KH; j++) {
            const int k = half * KH + j;
            ulonglong2 qa = sKC[k][0];
            u64 t0 = add2(fma2(qa.x, x2a, qa.y), A0[j]);    // log2-domain exponent
            u64 t1 = add2(fma2(qa.x, x2b, qa.y), A1[j]);
            float e00, e01, e10, e11;
            upk(t0, e00, e01); upk(t1, e10, e11);
            u64 s0 = pk(ex2f(e00), ex2f(e01));
            u64 s1 = pk(ex2f(e10), ex2f(e11));
            u64 o0 = fma2(s0, NEG1p, ONEp);                 // 1 - s
            u64 o1 = fma2(s1, NEG1p, ONEp);
            ulonglong2 qb = sKC[k][1];
            ulonglong2 qc = sKC[k][2];
            O0 = mul2(O0, o0);                              O1 = mul2(O1, o1);
            P00 = mul2(P00, fma2(qb.x, s0, o0));            P10 = mul2(P10, fma2(qb.x, s1, o1));
            P01 = mul2(P01, fma2(qb.y, s0, o0));            P11 = mul2(P11, fma2(qb.y, s1, o1));
            P02 = mul2(P02, fma2(qc.x, s0, o0));            P12 = mul2(P12, fma2(qc.x, s1, o1));
            P03 = mul2(P03, fma2(qc.y, s0, o0));            P13 = mul2(P13, fma2(qc.y, s1, o1));
        }
    }

    const u64 nO0 = mul2(O0, NEG1p), nO1 = mul2(O1, NEG1p);
    u64 f00 = add2(P00, nO0), f01 = add2(P01, nO0), f02 = add2(P02, nO0), f03 = add2(P03, nO0);
    u64 f10 = add2(P10, nO1), f11 = add2(P11, nO1), f12 = add2(P12, nO1), f13 = add2(P13, nO1);
    u64 sum0 = add2(add2(add2(f00, f01), add2(f02, f03)), O0);
    u64 sum1 = add2(add2(add2(f10, f11), add2(f12, f13)), O1);
    float sa, sb, sc2, sd;
    upk(sum0, sa, sb); upk(sum1, sc2, sd);
    const u64 inv0 = pk(rcpf(sa), rcpf(sb));
    const u64 inv1 = pk(rcpf(sc2), rcpf(sd));

    ulonglong2* ob = (ulonglong2*)out + ((size_t)b * (MM + 1) << 16) + sq;
    ob[(size_t)0 << 16] = make_ulonglong2(mul2(f00, inv0), mul2(f10, inv1));
    ob[(size_t)1 << 16] = make_ulonglong2(mul2(f01, inv0), mul2(f11, inv1));
    ob[(size_t)2 << 16] = make_ulonglong2(mul2(f02, inv0), mul2(f12, inv1));
    ob[(size_t)3 << 16] = make_ulonglong2(mul2(f03, inv0), mul2(f13, inv1));
    ob[(size_t)4 << 16] = make_ulonglong2(mul2(O0,  inv0), mul2(O1,  inv1));
}

extern "C" void kernel_launch(void* const* d_in, const int* in_sizes, int n_in,
                              void* d_out, int out_size)
{
    const float* x     = (const float*)d_in[0];
    const float* Wp    = (const float*)d_in[1];
    const float* BETA  = (const float*)d_in[2];
    const float* alpha = (const float*)d_in[3];
    const float* gamma = (const float*)d_in[4];
    float* out = (float*)d_out;

    ds_kernel<<<NTHR / BLK, BLK>>>(x, Wp, BETA, alpha, gamma, out);
}